// round 16
// baseline (speedup 1.0000x reference)
#include <cuda_runtime.h>
#include <cuda_fp16.h>
#include <cstdint>

#define DD 128
#define NMAX 50176
#define EMAX 800256

// ---------------- scratch (__device__ globals; no allocation) ----------------
__device__ float  g_ht[(size_t)NMAX * DD];    // post-linear h (fp32 master)
__device__ __half g_hth[(size_t)NMAX * DD];   // fp16 shadow for agg pass-2 reads
__device__ float  g_h2[(size_t)NMAX * DD];    // aggregated h (next gemm input)
__device__ float  g_sl[NMAX], g_sr[NMAX];
__device__ float  g_ew[EMAX];                 // cached edge scores
__device__ int    g_deg[NMAX];
__device__ int    g_off[NMAX + 1];
__device__ int    g_pos[NMAX];
__device__ int    g_col[EMAX];

// ---------------- CSR build ----------------
__global__ void k_count(const int* __restrict__ src, int E) {
    int i = blockIdx.x * blockDim.x + threadIdx.x;
    int e4 = E >> 2;
    if (i < e4) {
        int4 s = ((const int4*)src)[i];
        atomicAdd(&g_deg[s.x], 1);
        atomicAdd(&g_deg[s.y], 1);
        atomicAdd(&g_deg[s.z], 1);
        atomicAdd(&g_deg[s.w], 1);
    } else {
        int k = e4 * 4 + (i - e4);
        if (k < E) atomicAdd(&g_deg[src[k]], 1);
    }
}
__global__ __launch_bounds__(1024) void k_scan(int N, int E) {
    __shared__ int sh[1024];
    int tid = threadIdx.x;
    int per = (N + 1023) >> 10;
    int s = tid * per;
    int e = s + per; if (e > N) e = N;
    int sum = 0;
    for (int i = s; i < e; i++) sum += g_deg[i];
    sh[tid] = sum;
    __syncthreads();
    for (int o = 1; o < 1024; o <<= 1) {
        int t = (tid >= o) ? sh[tid - o] : 0;
        __syncthreads();
        sh[tid] += t;
        __syncthreads();
    }
    int run = sh[tid] - sum;
    for (int i = s; i < e; i++) { g_off[i] = run; g_pos[i] = run; run += g_deg[i]; }
    if (tid == 1023) g_off[N] = E;
}
__global__ void k_scatter(const int* __restrict__ src, const int* __restrict__ dst, int E) {
    int i = blockIdx.x * blockDim.x + threadIdx.x;
    int e4 = E >> 2;
    if (i < e4) {
        int4 s = ((const int4*)src)[i];
        int4 d = ((const int4*)dst)[i];
        g_col[atomicAdd(&g_pos[s.x], 1)] = d.x;
        g_col[atomicAdd(&g_pos[s.y], 1)] = d.y;
        g_col[atomicAdd(&g_pos[s.z], 1)] = d.z;
        g_col[atomicAdd(&g_pos[s.w], 1)] = d.w;
    } else {
        int k = e4 * 4 + (i - e4);
        if (k < E) g_col[atomicAdd(&g_pos[src[k]], 1)] = dst[k];
    }
}

// ---------------- GEMM: ht = leaky_relu(in @ W + b) + fused dots --------------
__global__ __launch_bounds__(256, 3) void k_gemm(
    const float* __restrict__ in,
    const float* __restrict__ W, const float* __restrict__ bias,
    const float* __restrict__ aw, int M)
{
    __shared__ float ws[64 * 128];   // 32 KB  W chunk [64k x 128n]
    __shared__ float hs[64 * 64];    // 16 KB  h tile  [64rows x 64k]

    int tid = threadIdx.x, warp = tid >> 5, lane = tid & 31;
    int r0 = blockIdx.x * 64;
    int c4 = lane * 4;

    float4 acc[8];
#pragma unroll
    for (int r = 0; r < 8; r++) acc[r] = make_float4(0.f, 0.f, 0.f, 0.f);

    for (int kc = 0; kc < DD; kc += 64) {
        const float4* wsrc = (const float4*)(W + (size_t)kc * DD);
        float4* wdst = (float4*)ws;
#pragma unroll
        for (int i = 0; i < 8; i++) wdst[tid + i * 256] = wsrc[tid + i * 256];
#pragma unroll
        for (int i = 0; i < 4; i++) {
            int idx = tid + i * 256;
            int row = idx >> 4;
            int c = idx & 15;
            float4 v = make_float4(0.f, 0.f, 0.f, 0.f);
            if (r0 + row < M)
                v = *(const float4*)(in + (size_t)(r0 + row) * DD + kc + c * 4);
            *(float4*)(hs + row * 64 + c * 4) = v;
        }
        __syncthreads();
        int wr = warp * 8;
#pragma unroll 8
        for (int k = 0; k < 64; k++) {
            float4 w4 = *(const float4*)(ws + k * DD + c4);
#pragma unroll
            for (int r = 0; r < 8; r++) {
                float a = hs[(wr + r) * 64 + k];
                acc[r].x += a * w4.x; acc[r].y += a * w4.y;
                acc[r].z += a * w4.z; acc[r].w += a * w4.w;
            }
        }
        __syncthreads();
    }

    float4 bb = *(const float4*)(bias + c4);
    float4 al = *(const float4*)(aw + c4);
    float4 ar = *(const float4*)(aw + DD + c4);
#pragma unroll
    for (int r = 0; r < 8; r++) {
        int row = r0 + warp * 8 + r;
        if (row < M) {
            float4 v = acc[r];
            v.x += bb.x; v.x = v.x > 0.f ? v.x : 0.2f * v.x;
            v.y += bb.y; v.y = v.y > 0.f ? v.y : 0.2f * v.y;
            v.z += bb.z; v.z = v.z > 0.f ? v.z : 0.2f * v.z;
            v.w += bb.w; v.w = v.w > 0.f ? v.w : 0.2f * v.w;
            *(float4*)(g_ht + (size_t)row * DD + c4) = v;
            // fp16 shadow row for agg pass-2 (8B per lane, coalesced 256B)
            __half2 p0 = __floats2half2_rn(v.x, v.y);
            __half2 p1 = __floats2half2_rn(v.z, v.w);
            uint2 hp;
            hp.x = *reinterpret_cast<uint32_t*>(&p0);
            hp.y = *reinterpret_cast<uint32_t*>(&p1);
            *(uint2*)(g_hth + (size_t)row * DD + c4) = hp;
            float dl = v.x * al.x + v.y * al.y + v.z * al.z + v.w * al.w;
            float dr = v.x * ar.x + v.y * ar.y + v.z * ar.z + v.w * ar.w;
#pragma unroll
            for (int o = 16; o; o >>= 1) {
                dl += __shfl_xor_sync(0xffffffffu, dl, o);
                dr += __shfl_xor_sync(0xffffffffu, dr, o);
            }
            if (lane == 0) { g_sl[row] = dl; g_sr[row] = dr; }
        }
    }
}

// ---------------- aggregation (warp per node; fp16 rows in pass 2) ------------
__global__ __launch_bounds__(256) void k_agg(
    float* __restrict__ out, const float* __restrict__ abp, int N)
{
    const __half* hth = g_hth;
    int gw = (blockIdx.x * blockDim.x + threadIdx.x) >> 5;
    int lane = threadIdx.x & 31;
    if (gw >= N) return;

    int base = g_off[gw], end = g_off[gw + 1];
    int c4 = lane * 4;
    float4 acc = make_float4(0.f, 0.f, 0.f, 0.f);

    if (end > base) {
        float ab = *abp;
        float sli = g_sl[gw];
        // pass 1: online softmax stats; cache e
        float m = -1e30f, s = 0.f;
        for (int k = base + lane; k < end; k += 32) {
            int d = g_col[k];
            float e = sli + g_sr[d] + ab;
            g_ew[k] = e;
            if (e > m) { s = s * __expf(m - e) + 1.f; m = e; }
            else        { s += __expf(e - m); }
        }
#pragma unroll
        for (int o = 16; o; o >>= 1) {
            float mo = __shfl_xor_sync(0xffffffffu, m, o);
            float so = __shfl_xor_sync(0xffffffffu, s, o);
            float mn = fmaxf(m, mo);
            s = s * __expf(m - mn) + so * __expf(mo - mn);
            m = mn;
        }
        float inv = 1.f / s;

        // pass 2: fp16 row reads (256B per row per warp), unroll x2
        int k = base;
        for (; k + 2 <= end; k += 2) {
            int d0 = g_col[k + 0];
            int d1 = g_col[k + 1];
            float e0 = g_ew[k + 0], e1 = g_ew[k + 1];
            uint2 q0 = *(const uint2*)(hth + (size_t)d0 * DD + c4);
            uint2 q1 = *(const uint2*)(hth + (size_t)d1 * DD + c4);
            float w0 = __expf(e0 - m) * inv;
            float w1 = __expf(e1 - m) * inv;
            float2 a0 = __half22float2(*reinterpret_cast<__half2*>(&q0.x));
            float2 b0 = __half22float2(*reinterpret_cast<__half2*>(&q0.y));
            float2 a1 = __half22float2(*reinterpret_cast<__half2*>(&q1.x));
            float2 b1 = __half22float2(*reinterpret_cast<__half2*>(&q1.y));
            acc.x += w0 * a0.x; acc.y += w0 * a0.y; acc.z += w0 * b0.x; acc.w += w0 * b0.y;
            acc.x += w1 * a1.x; acc.y += w1 * a1.y; acc.z += w1 * b1.x; acc.w += w1 * b1.y;
        }
        for (; k < end; k++) {
            int d = g_col[k];
            float w = __expf(g_ew[k] - m) * inv;
            uint2 q = *(const uint2*)(hth + (size_t)d * DD + c4);
            float2 a = __half22float2(*reinterpret_cast<__half2*>(&q.x));
            float2 b = __half22float2(*reinterpret_cast<__half2*>(&q.y));
            acc.x += w * a.x; acc.y += w * a.y; acc.z += w * b.x; acc.w += w * b.y;
        }
    }
    acc.x = fmaxf(acc.x, 0.f);
    acc.y = fmaxf(acc.y, 0.f);
    acc.z = fmaxf(acc.z, 0.f);
    acc.w = fmaxf(acc.w, 0.f);
    *(float4*)(out + (size_t)gw * DD + c4) = acc;
}

// ---------------- launch: single stream -------------------------------------
extern "C" void kernel_launch(void* const* d_in, const int* in_sizes, int n_in,
                              void* d_out, int out_size)
{
    const float* x      = (const float*)d_in[0];
    const int*   esrc   = (const int*)d_in[1];
    const int*   edst   = (const int*)d_in[2];
    const float* lin_w  = (const float*)d_in[3];
    const float* lin_b  = (const float*)d_in[4];
    const float* attn_w = (const float*)d_in[5];
    const float* attn_b = (const float*)d_in[6];

    int N = in_sizes[0] / DD;
    int E = in_sizes[1];

    void* degp = nullptr;
    cudaGetSymbolAddress(&degp, g_deg);
    float* h2p = nullptr;
    cudaGetSymbolAddress((void**)&h2p, g_h2);

    int gB = (N + 63) / 64;
    int aB = (N + 7) / 8;
    int cT = (E >> 2) + (E & 3);

    cudaMemsetAsync(degp, 0, (size_t)N * sizeof(int), 0);
    k_count<<<(cT + 255) / 256, 256>>>(esrc, E);
    k_scan<<<1, 1024>>>(N, E);
    k_scatter<<<(cT + 255) / 256, 256>>>(esrc, edst, E);

    k_gemm<<<gB, 256>>>(x, lin_w, lin_b, attn_w, N);
    k_agg<<<aB, 256>>>(h2p, attn_b + 0, N);
    k_gemm<<<gB, 256>>>(h2p, lin_w + (size_t)1 * DD * DD, lin_b + DD,
                        attn_w + (size_t)1 * 2 * DD, N);
    k_agg<<<aB, 256>>>(h2p, attn_b + 1, N);
    k_gemm<<<gB, 256>>>(h2p, lin_w + (size_t)2 * DD * DD, lin_b + 2 * DD,
                        attn_w + (size_t)2 * 2 * DD, N);
    k_agg<<<aB, 256>>>((float*)d_out, attn_b + 2, N);
}

// round 17
// speedup vs baseline: 1.1971x; 1.1971x over previous
#include <cuda_runtime.h>
#include <cuda_fp16.h>
#include <cstdint>

#define DD 128
#define NMAX 50176
#define EMAX 800256
#define NBMAX 64

// ---------------- scratch (__device__ globals; no allocation) ----------------
__device__ float  g_ht[(size_t)NMAX * DD];    // post-linear h (fp32 master)
__device__ __half g_hth[(size_t)NMAX * DD];   // fp16 shadow for agg pass-2 reads
__device__ float  g_h2[(size_t)NMAX * DD];    // aggregated h (next gemm input)
__device__ float  g_sl[NMAX], g_sr[NMAX];
__device__ float  g_ew[EMAX];                 // cached edge scores
__device__ int    g_deg[NMAX];
__device__ int    g_off[NMAX + 1];
__device__ int    g_pos[NMAX];
__device__ int    g_bsum[NBMAX];
__device__ int    g_col[EMAX];

// ---------------- CSR build ----------------
__global__ void k_count(const int* __restrict__ src, int E) {
    int i = blockIdx.x * blockDim.x + threadIdx.x;
    int e4 = E >> 2;
    if (i < e4) {
        int4 s = ((const int4*)src)[i];
        atomicAdd(&g_deg[s.x], 1);
        atomicAdd(&g_deg[s.y], 1);
        atomicAdd(&g_deg[s.z], 1);
        atomicAdd(&g_deg[s.w], 1);
    } else {
        int k = e4 * 4 + (i - e4);
        if (k < E) atomicAdd(&g_deg[src[k]], 1);
    }
}
// multi-block scan (R1 version — parallel across SMs)
__global__ __launch_bounds__(1024) void k_scanA(int N) {
    __shared__ int sh[1024];
    int i = blockIdx.x * 1024 + threadIdx.x;
    int v = (i < N) ? g_deg[i] : 0;
    sh[threadIdx.x] = v;
    __syncthreads();
    for (int o = 1; o < 1024; o <<= 1) {
        int t = (threadIdx.x >= (unsigned)o) ? sh[threadIdx.x - o] : 0;
        __syncthreads();
        sh[threadIdx.x] += t;
        __syncthreads();
    }
    if (i < N) g_off[i] = sh[threadIdx.x] - v;   // block-local exclusive
    if (threadIdx.x == 1023) g_bsum[blockIdx.x] = sh[1023];
}
__global__ void k_scanB(int nb) {
    if (threadIdx.x == 0) {
        int run = 0;
        for (int b = 0; b < nb; b++) { int t = g_bsum[b]; g_bsum[b] = run; run += t; }
    }
}
__global__ void k_scanC(int N, int E) {
    int i = blockIdx.x * blockDim.x + threadIdx.x;
    if (i < N) {
        int v = g_off[i] + g_bsum[i >> 10];
        g_off[i] = v;
        g_pos[i] = v;
    } else if (i == N) {
        g_off[N] = E;
    }
}
__global__ void k_scatter(const int* __restrict__ src, const int* __restrict__ dst, int E) {
    int i = blockIdx.x * blockDim.x + threadIdx.x;
    int e4 = E >> 2;
    if (i < e4) {
        int4 s = ((const int4*)src)[i];
        int4 d = ((const int4*)dst)[i];
        g_col[atomicAdd(&g_pos[s.x], 1)] = d.x;
        g_col[atomicAdd(&g_pos[s.y], 1)] = d.y;
        g_col[atomicAdd(&g_pos[s.z], 1)] = d.z;
        g_col[atomicAdd(&g_pos[s.w], 1)] = d.w;
    } else {
        int k = e4 * 4 + (i - e4);
        if (k < E) g_col[atomicAdd(&g_pos[src[k]], 1)] = dst[k];
    }
}

// ---------------- GEMM: ht = leaky_relu(in @ W + b) + fused dots --------------
__global__ __launch_bounds__(256, 3) void k_gemm(
    const float* __restrict__ in,
    const float* __restrict__ W, const float* __restrict__ bias,
    const float* __restrict__ aw, int M)
{
    __shared__ float ws[64 * 128];   // 32 KB  W chunk [64k x 128n]
    __shared__ float hs[64 * 64];    // 16 KB  h tile  [64rows x 64k]

    int tid = threadIdx.x, warp = tid >> 5, lane = tid & 31;
    int r0 = blockIdx.x * 64;
    int c4 = lane * 4;

    float4 acc[8];
#pragma unroll
    for (int r = 0; r < 8; r++) acc[r] = make_float4(0.f, 0.f, 0.f, 0.f);

    for (int kc = 0; kc < DD; kc += 64) {
        const float4* wsrc = (const float4*)(W + (size_t)kc * DD);
        float4* wdst = (float4*)ws;
#pragma unroll
        for (int i = 0; i < 8; i++) wdst[tid + i * 256] = wsrc[tid + i * 256];
#pragma unroll
        for (int i = 0; i < 4; i++) {
            int idx = tid + i * 256;
            int row = idx >> 4;
            int c = idx & 15;
            float4 v = make_float4(0.f, 0.f, 0.f, 0.f);
            if (r0 + row < M)
                v = *(const float4*)(in + (size_t)(r0 + row) * DD + kc + c * 4);
            *(float4*)(hs + row * 64 + c * 4) = v;
        }
        __syncthreads();
        int wr = warp * 8;
#pragma unroll 8
        for (int k = 0; k < 64; k++) {
            float4 w4 = *(const float4*)(ws + k * DD + c4);
#pragma unroll
            for (int r = 0; r < 8; r++) {
                float a = hs[(wr + r) * 64 + k];
                acc[r].x += a * w4.x; acc[r].y += a * w4.y;
                acc[r].z += a * w4.z; acc[r].w += a * w4.w;
            }
        }
        __syncthreads();
    }

    float4 bb = *(const float4*)(bias + c4);
    float4 al = *(const float4*)(aw + c4);
    float4 ar = *(const float4*)(aw + DD + c4);
#pragma unroll
    for (int r = 0; r < 8; r++) {
        int row = r0 + warp * 8 + r;
        if (row < M) {
            float4 v = acc[r];
            v.x += bb.x; v.x = v.x > 0.f ? v.x : 0.2f * v.x;
            v.y += bb.y; v.y = v.y > 0.f ? v.y : 0.2f * v.y;
            v.z += bb.z; v.z = v.z > 0.f ? v.z : 0.2f * v.z;
            v.w += bb.w; v.w = v.w > 0.f ? v.w : 0.2f * v.w;
            *(float4*)(g_ht + (size_t)row * DD + c4) = v;
            // fp16 shadow row for agg pass-2 (8B per lane, coalesced 256B)
            __half2 p0 = __floats2half2_rn(v.x, v.y);
            __half2 p1 = __floats2half2_rn(v.z, v.w);
            uint2 hp;
            hp.x = *reinterpret_cast<uint32_t*>(&p0);
            hp.y = *reinterpret_cast<uint32_t*>(&p1);
            *(uint2*)(g_hth + (size_t)row * DD + c4) = hp;
            float dl = v.x * al.x + v.y * al.y + v.z * al.z + v.w * al.w;
            float dr = v.x * ar.x + v.y * ar.y + v.z * ar.z + v.w * ar.w;
#pragma unroll
            for (int o = 16; o; o >>= 1) {
                dl += __shfl_xor_sync(0xffffffffu, dl, o);
                dr += __shfl_xor_sync(0xffffffffu, dr, o);
            }
            if (lane == 0) { g_sl[row] = dl; g_sr[row] = dr; }
        }
    }
}

// ---------------- aggregation (warp per node; fp16 rows in pass 2) ------------
__global__ __launch_bounds__(256) void k_agg(
    float* __restrict__ out, const float* __restrict__ abp, int N)
{
    const __half* hth = g_hth;
    int gw = (blockIdx.x * blockDim.x + threadIdx.x) >> 5;
    int lane = threadIdx.x & 31;
    if (gw >= N) return;

    int base = g_off[gw], end = g_off[gw + 1];
    int c4 = lane * 4;
    float4 acc = make_float4(0.f, 0.f, 0.f, 0.f);

    if (end > base) {
        float ab = *abp;
        float sli = g_sl[gw];
        // pass 1: online softmax stats; cache e (coalesced writes)
        float m = -1e30f, s = 0.f;
        for (int k = base + lane; k < end; k += 32) {
            int d = g_col[k];
            float e = sli + g_sr[d] + ab;
            g_ew[k] = e;
            if (e > m) { s = s * __expf(m - e) + 1.f; m = e; }
            else        { s += __expf(e - m); }
        }
#pragma unroll
        for (int o = 16; o; o >>= 1) {
            float mo = __shfl_xor_sync(0xffffffffu, m, o);
            float so = __shfl_xor_sync(0xffffffffu, s, o);
            float mn = fmaxf(m, mo);
            s = s * __expf(m - mn) + so * __expf(mo - mn);
            m = mn;
        }
        float inv = 1.f / s;

        // pass 2: fp16 row reads (256B per row per warp), unroll x2
        int k = base;
        for (; k + 2 <= end; k += 2) {
            int d0 = g_col[k + 0];
            int d1 = g_col[k + 1];
            float e0 = g_ew[k + 0], e1 = g_ew[k + 1];
            uint2 q0 = *(const uint2*)(hth + (size_t)d0 * DD + c4);
            uint2 q1 = *(const uint2*)(hth + (size_t)d1 * DD + c4);
            float w0 = __expf(e0 - m) * inv;
            float w1 = __expf(e1 - m) * inv;
            float2 a0 = __half22float2(*reinterpret_cast<__half2*>(&q0.x));
            float2 b0 = __half22float2(*reinterpret_cast<__half2*>(&q0.y));
            float2 a1 = __half22float2(*reinterpret_cast<__half2*>(&q1.x));
            float2 b1 = __half22float2(*reinterpret_cast<__half2*>(&q1.y));
            acc.x += w0 * a0.x; acc.y += w0 * a0.y; acc.z += w0 * b0.x; acc.w += w0 * b0.y;
            acc.x += w1 * a1.x; acc.y += w1 * a1.y; acc.z += w1 * b1.x; acc.w += w1 * b1.y;
        }
        for (; k < end; k++) {
            int d = g_col[k];
            float w = __expf(g_ew[k] - m) * inv;
            uint2 q = *(const uint2*)(hth + (size_t)d * DD + c4);
            float2 a = __half22float2(*reinterpret_cast<__half2*>(&q.x));
            float2 b = __half22float2(*reinterpret_cast<__half2*>(&q.y));
            acc.x += w * a.x; acc.y += w * a.y; acc.z += w * b.x; acc.w += w * b.y;
        }
    }
    acc.x = fmaxf(acc.x, 0.f);
    acc.y = fmaxf(acc.y, 0.f);
    acc.z = fmaxf(acc.z, 0.f);
    acc.w = fmaxf(acc.w, 0.f);
    *(float4*)(out + (size_t)gw * DD + c4) = acc;
}

// ---------------- launch: single stream -------------------------------------
extern "C" void kernel_launch(void* const* d_in, const int* in_sizes, int n_in,
                              void* d_out, int out_size)
{
    const float* x      = (const float*)d_in[0];
    const int*   esrc   = (const int*)d_in[1];
    const int*   edst   = (const int*)d_in[2];
    const float* lin_w  = (const float*)d_in[3];
    const float* lin_b  = (const float*)d_in[4];
    const float* attn_w = (const float*)d_in[5];
    const float* attn_b = (const float*)d_in[6];

    int N = in_sizes[0] / DD;
    int E = in_sizes[1];
    int nb = (N + 1023) / 1024;

    void* degp = nullptr;
    cudaGetSymbolAddress(&degp, g_deg);
    float* h2p = nullptr;
    cudaGetSymbolAddress((void**)&h2p, g_h2);

    int gB = (N + 63) / 64;
    int aB = (N + 7) / 8;
    int cT = (E >> 2) + (E & 3);

    // CSR build — multi-block scan (the R2 single-block scan was a ~55us bug)
    cudaMemsetAsync(degp, 0, (size_t)N * sizeof(int), 0);
    k_count<<<(cT + 255) / 256, 256>>>(esrc, E);
    k_scanA<<<nb, 1024>>>(N);
    k_scanB<<<1, 32>>>(nb);
    k_scanC<<<(N + 256) / 256, 256>>>(N, E);
    k_scatter<<<(cT + 255) / 256, 256>>>(esrc, edst, E);

    // layer 0
    k_gemm<<<gB, 256>>>(x, lin_w, lin_b, attn_w, N);
    k_agg<<<aB, 256>>>(h2p, attn_b + 0, N);
    // layer 1
    k_gemm<<<gB, 256>>>(h2p, lin_w + (size_t)1 * DD * DD, lin_b + DD,
                        attn_w + (size_t)1 * 2 * DD, N);
    k_agg<<<aB, 256>>>(h2p, attn_b + 1, N);
    // layer 2
    k_gemm<<<gB, 256>>>(h2p, lin_w + (size_t)2 * DD * DD, lin_b + 2 * DD,
                        attn_w + (size_t)2 * 2 * DD, N);
    k_agg<<<aB, 256>>>((float*)d_out, attn_b + 2, N);
}